// round 2
// baseline (speedup 1.0000x reference)
#include <cuda_runtime.h>

// Fused: gather+sqdiff -> [64,256] tile -> GEMM(w1)+relu -> GEMM(w2)+relu -> dot(w3)
// Activations live transposed in smem: in_T[k][r] with pitch 65 (odd -> conflict-free
// column reads; a-loads in the GEMM are warp-broadcast so pitch doesn't matter there).

#define D        256
#define TILE_M   64
#define THREADS  256
#define KC       32
#define PITCH    65

#define SMEM_IN_FLOATS  (D * PITCH)        // 16640
#define SMEM_W_FLOATS   (KC * D)           // 8192
#define SMEM_RED_FLOATS (4 * TILE_M)       // 256
#define SMEM_BYTES ((SMEM_IN_FLOATS + SMEM_W_FLOATS + SMEM_RED_FLOATS) * 4)

__global__ __launch_bounds__(THREADS, 2)
void fused_mlp_kernel(const int* __restrict__ pv, const int* __restrict__ qv,
                      const float* __restrict__ E,
                      const float* __restrict__ w1, const float* __restrict__ b1,
                      const float* __restrict__ w2, const float* __restrict__ b2,
                      const float* __restrict__ w3, const float* __restrict__ b3,
                      float* __restrict__ out, int M)
{
    extern __shared__ float smem[];
    float* in_T = smem;                      // [D][PITCH]  activations (transposed)
    float* wbuf = smem + SMEM_IN_FLOATS;     // [KC][D]     weight chunk
    float* red  = wbuf + SMEM_W_FLOATS;      // [4][TILE_M] layer-3 partials

    const int t  = threadIdx.x;
    const int m0 = blockIdx.x * TILE_M;
    const int rg = t >> 5;                   // 0..7  : rows rg*8 .. rg*8+7
    const int cg = t & 31;                   // 0..31 : cols cg*8 .. cg*8+7

    // ---------------- gather + squared diff, transposed store ----------------
    #pragma unroll
    for (int it = 0; it < 16; ++it) {
        int idx = it * THREADS + t;          // 0..4095 over (row, k4)
        int r   = idx >> 6;                  // 0..63
        int k4  = idx & 63;                  // float4 index within row
        int gi  = m0 + r;
        int pi  = (gi < M) ? pv[gi] : 0;
        int qi  = (gi < M) ? qv[gi] : 0;
        float4 a = *(const float4*)(E + (size_t)pi * D + (k4 << 2));
        float4 b = *(const float4*)(E + (size_t)qi * D + (k4 << 2));
        float d0 = a.x - b.x, d1 = a.y - b.y, d2 = a.z - b.z, d3 = a.w - b.w;
        int k = k4 << 2;
        in_T[(k + 0) * PITCH + r] = d0 * d0;
        in_T[(k + 1) * PITCH + r] = d1 * d1;
        in_T[(k + 2) * PITCH + r] = d2 * d2;
        in_T[(k + 3) * PITCH + r] = d3 * d3;
    }

    // ---------------- two hidden layers: [64,256] @ [256,256] + bias, relu ----
    #pragma unroll 1
    for (int layer = 0; layer < 2; ++layer) {
        const float* w = (layer == 0) ? w1 : w2;
        const float* b = (layer == 0) ? b1 : b2;

        float acc[8][8];
        #pragma unroll
        for (int i = 0; i < 8; ++i)
            #pragma unroll
            for (int j = 0; j < 8; ++j) acc[i][j] = 0.f;

        #pragma unroll 1
        for (int kc0 = 0; kc0 < D; kc0 += KC) {
            __syncthreads();                 // previous chunk fully consumed
            // stage weight chunk [KC][D] (row-major, straight float4 copy)
            {
                const float4* wsrc = (const float4*)(w + kc0 * D);
                float4*       wdst = (float4*)wbuf;
                #pragma unroll
                for (int i = 0; i < (KC * D / 4) / THREADS; ++i)   // 8
                    wdst[i * THREADS + t] = wsrc[i * THREADS + t];
            }
            __syncthreads();

            #pragma unroll 8
            for (int kk = 0; kk < KC; ++kk) {
                const float* arow = &in_T[(kc0 + kk) * PITCH + (rg << 3)];
                float a0 = arow[0], a1 = arow[1], a2 = arow[2], a3 = arow[3];
                float a4 = arow[4], a5 = arow[5], a6 = arow[6], a7 = arow[7];
                float4 wv0 = *(const float4*)&wbuf[kk * D + (cg << 3)];
                float4 wv1 = *(const float4*)&wbuf[kk * D + (cg << 3) + 4];
                float av[8] = {a0, a1, a2, a3, a4, a5, a6, a7};
                float wv[8] = {wv0.x, wv0.y, wv0.z, wv0.w, wv1.x, wv1.y, wv1.z, wv1.w};
                #pragma unroll
                for (int i = 0; i < 8; ++i)
                    #pragma unroll
                    for (int j = 0; j < 8; ++j)
                        acc[i][j] = fmaf(av[i], wv[j], acc[i][j]);
            }
        }
        __syncthreads();                     // everyone done reading in_T

        // bias + relu + transposed writeback (h becomes next layer's input)
        #pragma unroll
        for (int j = 0; j < 8; ++j) {
            int c = (cg << 3) + j;
            float bj = b[c];
            #pragma unroll
            for (int i = 0; i < 8; ++i) {
                float v = acc[i][j] + bj;
                in_T[c * PITCH + (rg << 3) + i] = fmaxf(v, 0.f);
            }
        }
        __syncthreads();
    }

    // ---------------- output layer: dot(h2[r,:], w3) + b3 --------------------
    {
        int r    = t & 63;
        int part = t >> 6;                   // 0..3, 64 k each
        int kb   = part * 64;
        float s = 0.f;
        #pragma unroll 8
        for (int k = 0; k < 64; ++k)
            s = fmaf(in_T[(kb + k) * PITCH + r], w3[kb + k], s);
        red[part * TILE_M + r] = s;
    }
    __syncthreads();
    if (t < TILE_M) {
        int gi = m0 + t;
        if (gi < M)
            out[gi] = red[t] + red[TILE_M + t] + red[2 * TILE_M + t]
                    + red[3 * TILE_M + t] + b3[0];
    }
}

extern "C" void kernel_launch(void* const* d_in, const int* in_sizes, int n_in,
                              void* d_out, int out_size)
{
    const int*   pv = (const int*)d_in[0];
    const int*   qv = (const int*)d_in[1];
    const float* E  = (const float*)d_in[2];
    const float* w1 = (const float*)d_in[3];
    const float* b1 = (const float*)d_in[4];
    const float* w2 = (const float*)d_in[5];
    const float* b2 = (const float*)d_in[6];
    const float* w3 = (const float*)d_in[7];
    const float* b3 = (const float*)d_in[8];
    float* out = (float*)d_out;
    const int M = in_sizes[0];

    static bool attr_set = false;
    if (!attr_set) {
        cudaFuncSetAttribute(fused_mlp_kernel,
                             cudaFuncAttributeMaxDynamicSharedMemorySize, SMEM_BYTES);
        attr_set = true;
    }

    int grid = (M + TILE_M - 1) / TILE_M;
    fused_mlp_kernel<<<grid, THREADS, SMEM_BYTES>>>(pv, qv, E, w1, b1, w2, b2,
                                                    w3, b3, out, M);
}

// round 5
// speedup vs baseline: 1.7904x; 1.7904x over previous
#include <cuda_runtime.h>
#include <cstdint>

#define D        256
#define TM       128
#define NTH      512

#define BCHUNK   32768        // one K=32 weight chunk, frag-packed

// smem layout (bytes)
#define SMEM_A     0          // A frags: 32 ktiles x 8 mtiles x 512B = 131072
#define SMEM_B     131072     // B ring: 3 x 32768 = 98304  (ends 229376)
#define SMEM_RED   0          // aliases A (disjoint live range)
#define SMEM_SB1   229376
#define SMEM_SB2   230400
#define SMEM_SW3   231424
#define SMEM_TOTAL 232448     // == 227 KB max dynamic smem

// frag-packed weights: [layer][kc(32)][npair(16)][lane(32)] x 16B
__device__ uint4 g_bpack[2 * 32 * 16 * 32];

__device__ __forceinline__ float to_tf32(float x) {
    float r;
    asm("cvt.rna.tf32.f32 %0, %1;" : "=f"(r) : "f"(x));
    return r;
}

__device__ __forceinline__ void mma_tf32(float* c, const uint4& a, uint32_t b0, uint32_t b1) {
    asm volatile("mma.sync.aligned.m16n8k8.row.col.f32.tf32.tf32.f32 "
                 "{%0,%1,%2,%3}, {%4,%5,%6,%7}, {%8,%9}, {%0,%1,%2,%3};"
                 : "+f"(c[0]), "+f"(c[1]), "+f"(c[2]), "+f"(c[3])
                 : "r"(a.x), "r"(a.y), "r"(a.z), "r"(a.w), "r"(b0), "r"(b1));
}

// ------------------------------------------------------------- weight prep
__global__ void pack_w_kernel(const float* __restrict__ w1, const float* __restrict__ w2) {
    int idx = blockIdx.x * 256 + threadIdx.x;          // 32768 slots
    int l    = idx >> 14;
    int kc   = (idx >> 9) & 31;
    int np   = (idx >> 5) & 15;
    int lane = idx & 31;
    const float* w = l ? w2 : w1;
    int k0 = kc * 8 + (lane & 3);
    int n0 = np * 16 + (lane >> 2);
    float4 v;
    v.x = to_tf32(w[(k0    ) * D + n0    ]);
    v.y = to_tf32(w[(k0 + 4) * D + n0    ]);
    v.z = to_tf32(w[(k0    ) * D + n0 + 8]);
    v.w = to_tf32(w[(k0 + 4) * D + n0 + 8]);
    g_bpack[idx] = *(uint4*)&v;
}

// ------------------------------------------------------------- helpers
__device__ __forceinline__ void issue_chunk(int g, char* smem, int t) {
    // chunk g (0..15) -> ring buffer g % 3
    const char* src = (const char*)g_bpack + (size_t)g * BCHUNK + (size_t)t * 64;
    char* dst = smem + SMEM_B + (g % 3) * BCHUNK + t * 64;
    size_t gsrc = (size_t)__cvta_generic_to_global((void*)src);
    uint32_t sdst;
    asm("{ .reg .u64 u; cvta.to.shared.u64 u, %1; cvt.u32.u64 %0, u; }" : "=r"(sdst) : "l"(dst));
    #pragma unroll
    for (int i = 0; i < 4; ++i)
        asm volatile("cp.async.cg.shared.global [%0], [%1], 16;"
                     :: "r"(sdst + i * 16), "l"(gsrc + i * 16));
    asm volatile("cp.async.commit_group;" ::: "memory");
}

// ------------------------------------------------------------- main kernel
__global__ __launch_bounds__(NTH, 1)
void fused_mlp_mma(const int* __restrict__ pv, const int* __restrict__ qv,
                   const float* __restrict__ E,
                   const float* __restrict__ b1v, const float* __restrict__ b2v,
                   const float* __restrict__ w3v, const float* __restrict__ b3v,
                   float* __restrict__ out, int M)
{
    extern __shared__ char smem[];
    const int t = threadIdx.x, lane = t & 31, wid = t >> 5;
    const int wm = wid >> 2, wn = wid & 3;         // warp grid 4(M) x 4(N)
    const int m0 = blockIdx.x * TM;

    float* sB1 = (float*)(smem + SMEM_SB1);
    float* sB2 = (float*)(smem + SMEM_SB2);
    float* sW3 = (float*)(smem + SMEM_SW3);
    if (t < D) { sB1[t] = b1v[t]; sB2[t] = b2v[t]; sW3[t] = w3v[t]; }

    issue_chunk(0, smem, t);
    issue_chunk(1, smem, t);

    // ---- gather + sqdiff -> A frags (tf32-rounded), conflict-free STS.128 ---
    {
        int chunk = t >> 6;                // k-range [chunk*32, +32)
        int rp = t & 63;
        int mt = rp >> 3, r8 = rp & 7;
        int r0 = mt * 16 + r8;
        int gi0 = m0 + r0, gi1 = gi0 + 8;
        if (gi0 >= M) gi0 = 0;
        if (gi1 >= M) gi1 = 0;
        const float4* P0 = (const float4*)(E + (size_t)pv[gi0] * D) + chunk * 8;
        const float4* Q0 = (const float4*)(E + (size_t)qv[gi0] * D) + chunk * 8;
        const float4* P1 = (const float4*)(E + (size_t)pv[gi1] * D) + chunk * 8;
        const float4* Q1 = (const float4*)(E + (size_t)qv[gi1] * D) + chunk * 8;
        #pragma unroll
        for (int kb = 0; kb < 4; ++kb) {
            float lo[8], hi[8];
            float4 pa = __ldg(P0 + kb * 2), pb = __ldg(P0 + kb * 2 + 1);
            float4 qa = __ldg(Q0 + kb * 2), qb = __ldg(Q0 + kb * 2 + 1);
            lo[0] = pa.x - qa.x; lo[1] = pa.y - qa.y; lo[2] = pa.z - qa.z; lo[3] = pa.w - qa.w;
            lo[4] = pb.x - qb.x; lo[5] = pb.y - qb.y; lo[6] = pb.z - qb.z; lo[7] = pb.w - qb.w;
            pa = __ldg(P1 + kb * 2); pb = __ldg(P1 + kb * 2 + 1);
            qa = __ldg(Q1 + kb * 2); qb = __ldg(Q1 + kb * 2 + 1);
            hi[0] = pa.x - qa.x; hi[1] = pa.y - qa.y; hi[2] = pa.z - qa.z; hi[3] = pa.w - qa.w;
            hi[4] = pb.x - qb.x; hi[5] = pb.y - qb.y; hi[6] = pb.z - qb.z; hi[7] = pb.w - qb.w;
            int kc = chunk * 4 + kb;
            char* base = smem + SMEM_A + (kc * 8 + mt) * 512;
            #pragma unroll
            for (int c2i = 0; c2i < 4; ++c2i) {
                int c2 = (c2i + (r8 >> 1)) & 3;    // phase rotation
                float4 v;
                v.x = to_tf32(lo[c2] * lo[c2]);
                v.y = to_tf32(hi[c2] * hi[c2]);
                v.z = to_tf32(lo[c2 + 4] * lo[c2 + 4]);
                v.w = to_tf32(hi[c2 + 4] * hi[c2 + 4]);
                *(float4*)(base + (((r8 << 2) | c2) * 16)) = v;
            }
        }
    }

    float acc[2][8][4];
    #pragma unroll
    for (int i = 0; i < 2; ++i)
        #pragma unroll
        for (int j = 0; j < 8; ++j)
            #pragma unroll
            for (int e = 0; e < 4; ++e) acc[i][j][e] = 0.f;

    // ---- 16 K-chunks: 8 per layer, 3-deep cp.async ring ---------------------
    #pragma unroll 1
    for (int g = 0; g < 16; ++g) {
        if (g == 8) {
            // layer-1 epilogue: acc -> bias+relu+tf32 -> A frags (in place).
            // sync: all warps must be done with layer-1 A reads first.
            __syncthreads();
            #pragma unroll
            for (int i = 0; i < 2; ++i) {
                int mt2 = wm * 2 + i;
                #pragma unroll
                for (int nt = 0; nt < 8; ++nt) {
                    int kc2 = wn * 8 + nt;
                    char* base = smem + SMEM_A + (kc2 * 8 + mt2) * 512;
                    #pragma unroll
                    for (int h = 0; h < 2; ++h)
                        #pragma unroll
                        for (int e = 0; e < 2; ++e) {
                            int cl = 2 * (lane & 3) + e;
                            int c = wn * 64 + nt * 8 + cl;
                            float v = fmaxf(acc[i][nt][h * 2 + e] + sB1[c], 0.f);
                            int lane2 = ((lane >> 2) << 2) | (cl & 3);
                            int j2 = h + 2 * ((cl >> 2) & 1);
                            *(float*)(base + lane2 * 16 + j2 * 4) = to_tf32(v);
                            acc[i][nt][h * 2 + e] = 0.f;
                        }
                }
            }
        }

        // chunk g resident (groups 0..g+1 issued so far; allow 1 pending)
        if (g < 15) asm volatile("cp.async.wait_group 1;" ::: "memory");
        else        asm volatile("cp.async.wait_group 0;" ::: "memory");
        __syncthreads();   // chunk g visible everywhere; iter g-1 reads all done

        // now safe: buffer (g+2)%3 == (g-1)%3, its consumer finished last iter
        if (g + 2 < 16) issue_chunk(g + 2, smem, t);

        const char* bbuf = smem + SMEM_B + (g % 3) * BCHUNK;
        #pragma unroll
        for (int kt = 0; kt < 4; ++kt) {
            int kc = (g & 7) * 4 + kt;
            uint4 af[2];
            #pragma unroll
            for (int i = 0; i < 2; ++i)
                af[i] = *(const uint4*)(smem + SMEM_A + (kc * 8 + wm * 2 + i) * 512 + lane * 16);
            uint4 bf[4];
            #pragma unroll
            for (int jp = 0; jp < 4; ++jp)
                bf[jp] = *(const uint4*)(bbuf + (kt * 16 + wn * 4 + jp) * 512 + lane * 16);
            #pragma unroll
            for (int i = 0; i < 2; ++i)
                #pragma unroll
                for (int jp = 0; jp < 4; ++jp) {
                    mma_tf32(acc[i][jp * 2 + 0], af[i], bf[jp].x, bf[jp].y);
                    mma_tf32(acc[i][jp * 2 + 1], af[i], bf[jp].z, bf[jp].w);
                }
        }
    }

    // ---- final: bias+relu, dot w3, reduce ----------------------------------
    {
        float rsum[4] = {0.f, 0.f, 0.f, 0.f};
        #pragma unroll
        for (int i = 0; i < 2; ++i)
            #pragma unroll
            for (int nt = 0; nt < 8; ++nt)
                #pragma unroll
                for (int h = 0; h < 2; ++h)
                    #pragma unroll
                    for (int e = 0; e < 2; ++e) {
                        int c = wn * 64 + nt * 8 + 2 * (lane & 3) + e;
                        float v = fmaxf(acc[i][nt][h * 2 + e] + sB2[c], 0.f);
                        rsum[i * 2 + h] = fmaf(v, sW3[c], rsum[i * 2 + h]);
                    }
        #pragma unroll
        for (int k = 0; k < 4; ++k) {
            rsum[k] += __shfl_xor_sync(0xffffffffu, rsum[k], 1);
            rsum[k] += __shfl_xor_sync(0xffffffffu, rsum[k], 2);
        }
        // red aliases SMEM_A bytes [0,2048): those frags (kc=0, mt 0..3) were
        // last read at g=8; slow warps at g=15 read kc>=28 (bytes >= 114688).
        float* red = (float*)(smem + SMEM_RED);
        if ((lane & 3) == 0) {
            #pragma unroll
            for (int i = 0; i < 2; ++i)
                #pragma unroll
                for (int h = 0; h < 2; ++h)
                    red[wn * 128 + wm * 32 + i * 16 + h * 8 + (lane >> 2)] = rsum[i * 2 + h];
        }
    }
    __syncthreads();
    if (t < TM) {
        int gi = m0 + t;
        float* red = (float*)(smem + SMEM_RED);
        if (gi < M)
            out[gi] = red[t] + red[128 + t] + red[256 + t] + red[384 + t] + __ldg(b3v);
    }
}

// ------------------------------------------------------------- launch
extern "C" void kernel_launch(void* const* d_in, const int* in_sizes, int n_in,
                              void* d_out, int out_size)
{
    const int*   pv = (const int*)d_in[0];
    const int*   qv = (const int*)d_in[1];
    const float* E  = (const float*)d_in[2];
    const float* w1 = (const float*)d_in[3];
    const float* b1 = (const float*)d_in[4];
    const float* w2 = (const float*)d_in[5];
    const float* b2 = (const float*)d_in[6];
    const float* w3 = (const float*)d_in[7];
    const float* b3 = (const float*)d_in[8];
    float* out = (float*)d_out;
    const int M = in_sizes[0];

    cudaFuncSetAttribute(fused_mlp_mma,
                         cudaFuncAttributeMaxDynamicSharedMemorySize, SMEM_TOTAL);

    pack_w_kernel<<<128, 256>>>(w1, w2);
    int grid = (M + TM - 1) / TM;
    fused_mlp_mma<<<grid, NTH, SMEM_TOTAL>>>(pv, qv, E, b1, b2, w3, b3, out, M);
}

// round 6
// speedup vs baseline: 2.9368x; 1.6403x over previous
#include <cuda_runtime.h>
#include <cuda_fp16.h>
#include <cstdint>

#define D        256
#define TM       128
#define NTH      512

#define BCHUNK   32768        // one K=64 weight chunk (4 ktiles), frag-packed fp16

// smem layout (bytes)
#define SMEM_A     0          // A fp16 row-major: 128 rows x 512B (swizzled) = 65536
#define SMEM_B     65536      // B ring: 4 x 32768 = 131072  (ends 196608)
#define SMEM_SB1   196608     // 256 floats
#define SMEM_SB2   197632
#define SMEM_SW3   198656
#define SMEM_RED   199680     // 512 floats
#define SMEM_TOTAL 201728

// frag-packed fp16 weights: [layer(2)][ktile(16)][slot(16)][lane(32)] x 16B
// slot s holds ntiles 2s, 2s+1; per lane: {b0(2s), b1(2s), b0(2s+1), b1(2s+1)}
__device__ uint4 g_bpack[2 * 16 * 16 * 32];

__device__ __forceinline__ uint32_t f2h2(float lo, float hi) {
    __half2 h = __floats2half2_rn(lo, hi);
    return *(uint32_t*)&h;
}

__device__ __forceinline__ void mma_f16(float* c, const uint32_t* a, uint32_t b0, uint32_t b1) {
    asm volatile("mma.sync.aligned.m16n8k16.row.col.f32.f16.f16.f32 "
                 "{%0,%1,%2,%3}, {%4,%5,%6,%7}, {%8,%9}, {%0,%1,%2,%3};"
                 : "+f"(c[0]), "+f"(c[1]), "+f"(c[2]), "+f"(c[3])
                 : "r"(a[0]), "r"(a[1]), "r"(a[2]), "r"(a[3]), "r"(b0), "r"(b1));
}

// ------------------------------------------------------------- weight prep
__global__ void pack_w_kernel(const float* __restrict__ w1, const float* __restrict__ w2) {
    int idx = blockIdx.x * 256 + threadIdx.x;      // 16384 uint4 slots
    int l    = idx >> 13;
    int kt   = (idx >> 9) & 15;
    int s    = (idx >> 5) & 15;
    int lane = idx & 31;
    const float* w = l ? w2 : w1;
    int g = lane >> 2, t = lane & 3;
    int k0 = kt * 16 + 2 * t;
    int na = 16 * s + g;          // ntile 2s
    int nb = na + 8;              // ntile 2s+1
    uint4 v;
    v.x = f2h2(w[(k0    ) * D + na], w[(k0 + 1) * D + na]);
    v.y = f2h2(w[(k0 + 8) * D + na], w[(k0 + 9) * D + na]);
    v.z = f2h2(w[(k0    ) * D + nb], w[(k0 + 1) * D + nb]);
    v.w = f2h2(w[(k0 + 8) * D + nb], w[(k0 + 9) * D + nb]);
    g_bpack[idx] = v;
}

// ------------------------------------------------------------- helpers
__device__ __forceinline__ void issue_chunk(int g, char* smem, int t) {
    // chunk g (0..7) -> ring buffer g & 3 ; 32KB, 64B per thread
    const char* src = (const char*)g_bpack + (size_t)g * BCHUNK + (size_t)t * 64;
    char* dst = smem + SMEM_B + (g & 3) * BCHUNK + t * 64;
    size_t gsrc = (size_t)__cvta_generic_to_global((void*)src);
    uint32_t sdst;
    asm("{ .reg .u64 u; cvta.to.shared.u64 u, %1; cvt.u32.u64 %0, u; }" : "=r"(sdst) : "l"(dst));
    #pragma unroll
    for (int i = 0; i < 4; ++i)
        asm volatile("cp.async.cg.shared.global [%0], [%1], 16;"
                     :: "r"(sdst + i * 16), "l"(gsrc + i * 16));
    asm volatile("cp.async.commit_group;" ::: "memory");
}

// A smem address: row-major fp16, 512B rows, 16B-unit swizzle u^(row&7)
__device__ __forceinline__ uint32_t a_addr(uint32_t sbA, int row, int unit) {
    return sbA + row * 512 + (((unsigned)(unit ^ (row & 7))) << 4);
}

// ------------------------------------------------------------- main kernel
__global__ __launch_bounds__(NTH, 1)
void fused_mlp_mma(const int* __restrict__ pv, const int* __restrict__ qv,
                   const float* __restrict__ E,
                   const float* __restrict__ b1v, const float* __restrict__ b2v,
                   const float* __restrict__ w3v, const float* __restrict__ b3v,
                   float* __restrict__ out, int M)
{
    extern __shared__ char smem[];
    uint32_t sbA;
    asm("{ .reg .u64 u; cvta.to.shared.u64 u, %1; cvt.u32.u64 %0, u; }" : "=r"(sbA) : "l"(smem));
    const int t = threadIdx.x, lane = t & 31, wid = t >> 5;
    const int wm = wid >> 2, wn = wid & 3;         // warp grid 4(M) x 4(N)
    const int m0 = blockIdx.x * TM;

    float* sB1 = (float*)(smem + SMEM_SB1);
    float* sB2 = (float*)(smem + SMEM_SB2);
    float* sW3 = (float*)(smem + SMEM_SW3);
    if (t < D) { sB1[t] = b1v[t]; sB2[t] = b2v[t]; sW3[t] = w3v[t]; }

    issue_chunk(0, smem, t);
    issue_chunk(1, smem, t);
    issue_chunk(2, smem, t);

    // ---- gather + sqdiff -> A rows (fp16), conflict-free STS.128 ------------
    {
        int r = t >> 2, part = t & 3;              // 4 threads per row, 64 cols each
        int gi = m0 + r;
        int pi = (gi < M) ? pv[gi] : 0;
        int qi = (gi < M) ? qv[gi] : 0;
        const float4* P = (const float4*)(E + (size_t)pi * D) + part * 16;
        const float4* Q = (const float4*)(E + (size_t)qi * D) + part * 16;
        #pragma unroll
        for (int jj = 0; jj < 8; ++jj) {
            float4 a0 = __ldg(P + 2 * jj),     b0 = __ldg(Q + 2 * jj);
            float4 a1 = __ldg(P + 2 * jj + 1), b1 = __ldg(Q + 2 * jj + 1);
            float d0 = a0.x - b0.x, d1 = a0.y - b0.y, d2 = a0.z - b0.z, d3 = a0.w - b0.w;
            float e0 = a1.x - b1.x, e1 = a1.y - b1.y, e2 = a1.z - b1.z, e3 = a1.w - b1.w;
            uint4 v;
            v.x = f2h2(d0 * d0, d1 * d1);
            v.y = f2h2(d2 * d2, d3 * d3);
            v.z = f2h2(e0 * e0, e1 * e1);
            v.w = f2h2(e2 * e2, e3 * e3);
            *(uint4*)(smem + (a_addr(sbA, r, part * 8 + jj) - sbA)) = v;
        }
    }

    float acc[2][8][4];
    #pragma unroll
    for (int i = 0; i < 2; ++i)
        #pragma unroll
        for (int j = 0; j < 8; ++j)
            #pragma unroll
            for (int e = 0; e < 4; ++e) acc[i][j][e] = 0.f;

    // ---- 8 K-chunks (K=64 each): 4 per layer, 4-deep cp.async ring ----------
    #pragma unroll 1
    for (int g = 0; g < 8; ++g) {
        if (g <= 5)      asm volatile("cp.async.wait_group 2;" ::: "memory");
        else if (g == 6) asm volatile("cp.async.wait_group 1;" ::: "memory");
        else             asm volatile("cp.async.wait_group 0;" ::: "memory");
        __syncthreads();            // chunk g visible; all warps past iter g-1

        if (g == 4) {
            // layer-1 epilogue: acc -> bias+relu -> fp16 A rows (in place)
            #pragma unroll
            for (int i = 0; i < 2; ++i) {
                int row0 = wm * 32 + i * 16 + (lane >> 2);
                #pragma unroll
                for (int j = 0; j < 8; ++j) {
                    int c0 = wn * 64 + j * 8 + 2 * (lane & 3);
                    float v00 = fmaxf(acc[i][j][0] + sB1[c0],     0.f);
                    float v01 = fmaxf(acc[i][j][1] + sB1[c0 + 1], 0.f);
                    float v10 = fmaxf(acc[i][j][2] + sB1[c0],     0.f);
                    float v11 = fmaxf(acc[i][j][3] + sB1[c0 + 1], 0.f);
                    int u = wn * 8 + j;
                    int off = (c0 & 7) * 2;
                    *(uint32_t*)(smem + (a_addr(sbA, row0,     u) - sbA) + off) = f2h2(v00, v01);
                    *(uint32_t*)(smem + (a_addr(sbA, row0 + 8, u) - sbA) + off) = f2h2(v10, v11);
                    acc[i][j][0] = acc[i][j][1] = acc[i][j][2] = acc[i][j][3] = 0.f;
                }
            }
            __syncthreads();        // A rewrite complete before layer-2 reads
        }

        if (g + 3 < 8) issue_chunk(g + 3, smem, t);   // buf (g-1)&3, consumed

        const char* bbuf = smem + SMEM_B + (g & 3) * BCHUNK;
        #pragma unroll
        for (int kk = 0; kk < 4; ++kk) {
            int ktl = (g & 3) * 4 + kk;               // layer-local ktile 0..15
            uint32_t a[2][4];
            #pragma unroll
            for (int i = 0; i < 2; ++i) {
                int row = (wm * 2 + i) * 16 + (lane & 15);
                uint32_t addr = a_addr(sbA, row, ktl * 2 + (lane >> 4));
                asm volatile("ldmatrix.sync.aligned.m8n8.x4.shared.b16 {%0,%1,%2,%3}, [%4];"
                             : "=r"(a[i][0]), "=r"(a[i][1]), "=r"(a[i][2]), "=r"(a[i][3])
                             : "r"(addr));
            }
            uint4 bf[4];
            #pragma unroll
            for (int jp = 0; jp < 4; ++jp)
                bf[jp] = *(const uint4*)(bbuf + ((kk * 16 + wn * 4 + jp) * 32 + lane) * 16);
            #pragma unroll
            for (int i = 0; i < 2; ++i)
                #pragma unroll
                for (int jp = 0; jp < 4; ++jp) {
                    mma_f16(acc[i][jp * 2 + 0], a[i], bf[jp].x, bf[jp].y);
                    mma_f16(acc[i][jp * 2 + 1], a[i], bf[jp].z, bf[jp].w);
                }
        }
    }

    // ---- final: bias+relu, dot w3, reduce ----------------------------------
    {
        float rsum[4] = {0.f, 0.f, 0.f, 0.f};
        #pragma unroll
        for (int i = 0; i < 2; ++i)
            #pragma unroll
            for (int j = 0; j < 8; ++j)
                #pragma unroll
                for (int h = 0; h < 2; ++h)
                    #pragma unroll
                    for (int e = 0; e < 2; ++e) {
                        int c = wn * 64 + j * 8 + 2 * (lane & 3) + e;
                        float v = fmaxf(acc[i][j][h * 2 + e] + sB2[c], 0.f);
                        rsum[i * 2 + h] = fmaf(v, sW3[c], rsum[i * 2 + h]);
                    }
        #pragma unroll
        for (int k = 0; k < 4; ++k) {
            rsum[k] += __shfl_xor_sync(0xffffffffu, rsum[k], 1);
            rsum[k] += __shfl_xor_sync(0xffffffffu, rsum[k], 2);
        }
        float* red = (float*)(smem + SMEM_RED);
        if ((lane & 3) == 0) {
            #pragma unroll
            for (int i = 0; i < 2; ++i)
                #pragma unroll
                for (int h = 0; h < 2; ++h)
                    red[wn * 128 + wm * 32 + i * 16 + h * 8 + (lane >> 2)] = rsum[i * 2 + h];
        }
    }
    __syncthreads();
    if (t < TM) {
        int gi = m0 + t;
        float* red = (float*)(smem + SMEM_RED);
        if (gi < M)
            out[gi] = red[t] + red[128 + t] + red[256 + t] + red[384 + t] + __ldg(b3v);
    }
}

// ------------------------------------------------------------- launch
extern "C" void kernel_launch(void* const* d_in, const int* in_sizes, int n_in,
                              void* d_out, int out_size)
{
    const int*   pv = (const int*)d_in[0];
    const int*   qv = (const int*)d_in[1];
    const float* E  = (const float*)d_in[2];
    const float* w1 = (const float*)d_in[3];
    const float* b1 = (const float*)d_in[4];
    const float* w2 = (const float*)d_in[5];
    const float* b2 = (const float*)d_in[6];
    const float* w3 = (const float*)d_in[7];
    const float* b3 = (const float*)d_in[8];
    float* out = (float*)d_out;
    const int M = in_sizes[0];

    cudaFuncSetAttribute(fused_mlp_mma,
                         cudaFuncAttributeMaxDynamicSharedMemorySize, SMEM_TOTAL);

    pack_w_kernel<<<64, 256>>>(w1, w2);
    int grid = (M + TM - 1) / TM;
    fused_mlp_mma<<<grid, NTH, SMEM_TOTAL>>>(pv, qv, E, b1, b2, w3, b3, out, M);
}

// round 7
// speedup vs baseline: 3.0525x; 1.0394x over previous
#include <cuda_runtime.h>
#include <cuda_fp16.h>
#include <cstdint>

#define D        256
#define TM       64
#define NTH      256

#define BCHUNK   16384        // one K=32 weight chunk (2 ktiles), frag-packed fp16

// smem layout (bytes)
#define SMEM_A     0          // A fp16 row-major: 64 rows x 512B (swizzled) = 32768
#define SMEM_B     32768      // B ring: 4 x 16384 = 65536  (ends 98304)
#define SMEM_SB1   98304      // 256 floats
#define SMEM_SB2   99328
#define SMEM_SW3   100352
#define SMEM_RED   101376     // 256 floats
#define SMEM_TOTAL 102400     // 2 CTAs/SM: 200KB <= 227KB

// frag-packed fp16 weights: [layer(2)][ktile(16)][slot(16)][lane(32)] x 16B
// slot s holds ntiles 2s, 2s+1; per lane: {b0(2s), b1(2s), b0(2s+1), b1(2s+1)}
// chunk g (K=32) = ktiles 2g, 2g+1 -> contiguous 16KB at g*BCHUNK.
__device__ uint4 g_bpack[2 * 16 * 16 * 32];

__device__ __forceinline__ uint32_t f2h2(float lo, float hi) {
    __half2 h = __floats2half2_rn(lo, hi);
    return *(uint32_t*)&h;
}

__device__ __forceinline__ void mma_f16(float* c, const uint32_t* a, uint32_t b0, uint32_t b1) {
    asm volatile("mma.sync.aligned.m16n8k16.row.col.f32.f16.f16.f32 "
                 "{%0,%1,%2,%3}, {%4,%5,%6,%7}, {%8,%9}, {%0,%1,%2,%3};"
                 : "+f"(c[0]), "+f"(c[1]), "+f"(c[2]), "+f"(c[3])
                 : "r"(a[0]), "r"(a[1]), "r"(a[2]), "r"(a[3]), "r"(b0), "r"(b1));
}

// ------------------------------------------------------------- weight prep
__global__ void pack_w_kernel(const float* __restrict__ w1, const float* __restrict__ w2) {
    int idx = blockIdx.x * 256 + threadIdx.x;      // 16384 uint4 slots
    int l    = idx >> 13;
    int kt   = (idx >> 9) & 15;
    int s    = (idx >> 5) & 15;
    int lane = idx & 31;
    const float* w = l ? w2 : w1;
    int g = lane >> 2, t = lane & 3;
    int k0 = kt * 16 + 2 * t;
    int na = 16 * s + g;
    int nb = na + 8;
    uint4 v;
    v.x = f2h2(w[(k0    ) * D + na], w[(k0 + 1) * D + na]);
    v.y = f2h2(w[(k0 + 8) * D + na], w[(k0 + 9) * D + na]);
    v.z = f2h2(w[(k0    ) * D + nb], w[(k0 + 1) * D + nb]);
    v.w = f2h2(w[(k0 + 8) * D + nb], w[(k0 + 9) * D + nb]);
    g_bpack[idx] = v;
}

// ------------------------------------------------------------- helpers
__device__ __forceinline__ void issue_chunk(int g, char* smem, int t) {
    // chunk g (0..15) -> ring buffer g & 3 ; 16KB, 64B per thread
    const char* src = (const char*)g_bpack + (size_t)g * BCHUNK + (size_t)t * 64;
    char* dst = smem + SMEM_B + (g & 3) * BCHUNK + t * 64;
    size_t gsrc = (size_t)__cvta_generic_to_global((void*)src);
    uint32_t sdst;
    asm("{ .reg .u64 u; cvta.to.shared.u64 u, %1; cvt.u32.u64 %0, u; }" : "=r"(sdst) : "l"(dst));
    #pragma unroll
    for (int i = 0; i < 4; ++i)
        asm volatile("cp.async.cg.shared.global [%0], [%1], 16;"
                     :: "r"(sdst + i * 16), "l"(gsrc + i * 16));
    asm volatile("cp.async.commit_group;" ::: "memory");
}

// A smem address: row-major fp16, 512B rows, 16B-unit swizzle u^(row&7)
__device__ __forceinline__ uint32_t a_addr(uint32_t sbA, int row, int unit) {
    return sbA + row * 512 + (((unsigned)(unit ^ (row & 7))) << 4);
}

// ------------------------------------------------------------- main kernel
__global__ __launch_bounds__(NTH, 2)
void fused_mlp_mma(const int* __restrict__ pv, const int* __restrict__ qv,
                   const float* __restrict__ E,
                   const float* __restrict__ b1v, const float* __restrict__ b2v,
                   const float* __restrict__ w3v, const float* __restrict__ b3v,
                   float* __restrict__ out, int M)
{
    extern __shared__ char smem[];
    uint32_t sbA;
    asm("{ .reg .u64 u; cvta.to.shared.u64 u, %1; cvt.u32.u64 %0, u; }" : "=r"(sbA) : "l"(smem));
    const int t = threadIdx.x, lane = t & 31, wid = t >> 5;
    const int wm = wid >> 2, wn = wid & 3;         // warp grid 2(M) x 4(N)
    const int m0 = blockIdx.x * TM;

    float* sB1 = (float*)(smem + SMEM_SB1);
    float* sB2 = (float*)(smem + SMEM_SB2);
    float* sW3 = (float*)(smem + SMEM_SW3);
    sB1[t] = b1v[t]; sB2[t] = b2v[t]; sW3[t] = w3v[t];   // NTH == D

    issue_chunk(0, smem, t);
    issue_chunk(1, smem, t);
    issue_chunk(2, smem, t);

    // ---- gather + sqdiff -> A rows (fp16), conflict-free STS.128 ------------
    {
        int r = t >> 2, part = t & 3;              // 4 threads per row, 64 cols each
        int gi = m0 + r;
        int pi = (gi < M) ? pv[gi] : 0;
        int qi = (gi < M) ? qv[gi] : 0;
        const float4* P = (const float4*)(E + (size_t)pi * D) + part * 16;
        const float4* Q = (const float4*)(E + (size_t)qi * D) + part * 16;
        #pragma unroll
        for (int jj = 0; jj < 8; ++jj) {
            float4 a0 = __ldg(P + 2 * jj),     b0 = __ldg(Q + 2 * jj);
            float4 a1 = __ldg(P + 2 * jj + 1), b1 = __ldg(Q + 2 * jj + 1);
            float d0 = a0.x - b0.x, d1 = a0.y - b0.y, d2 = a0.z - b0.z, d3 = a0.w - b0.w;
            float e0 = a1.x - b1.x, e1 = a1.y - b1.y, e2 = a1.z - b1.z, e3 = a1.w - b1.w;
            uint4 v;
            v.x = f2h2(d0 * d0, d1 * d1);
            v.y = f2h2(d2 * d2, d3 * d3);
            v.z = f2h2(e0 * e0, e1 * e1);
            v.w = f2h2(e2 * e2, e3 * e3);
            *(uint4*)(smem + (a_addr(sbA, r, part * 8 + jj) - sbA)) = v;
        }
    }

    float acc[2][8][4];
    #pragma unroll
    for (int i = 0; i < 2; ++i)
        #pragma unroll
        for (int j = 0; j < 8; ++j)
            #pragma unroll
            for (int e = 0; e < 4; ++e) acc[i][j][e] = 0.f;

    // ---- 16 K-chunks (K=32): 8 per layer, 4-deep cp.async ring --------------
    #pragma unroll 1
    for (int g = 0; g < 16; ++g) {
        if (g <= 13)     asm volatile("cp.async.wait_group 2;" ::: "memory");
        else if (g == 14) asm volatile("cp.async.wait_group 1;" ::: "memory");
        else             asm volatile("cp.async.wait_group 0;" ::: "memory");
        __syncthreads();            // chunk g visible; all warps past iter g-1

        if (g == 8) {
            // layer-1 epilogue: acc -> bias+relu -> fp16 A rows (in place)
            #pragma unroll
            for (int i = 0; i < 2; ++i) {
                int row0 = wm * 32 + i * 16 + (lane >> 2);
                #pragma unroll
                for (int j = 0; j < 8; ++j) {
                    int c0 = wn * 64 + j * 8 + 2 * (lane & 3);
                    float v00 = fmaxf(acc[i][j][0] + sB1[c0],     0.f);
                    float v01 = fmaxf(acc[i][j][1] + sB1[c0 + 1], 0.f);
                    float v10 = fmaxf(acc[i][j][2] + sB1[c0],     0.f);
                    float v11 = fmaxf(acc[i][j][3] + sB1[c0 + 1], 0.f);
                    int u = wn * 8 + j;
                    int off = (c0 & 7) * 2;
                    *(uint32_t*)(smem + (a_addr(sbA, row0,     u) - sbA) + off) = f2h2(v00, v01);
                    *(uint32_t*)(smem + (a_addr(sbA, row0 + 8, u) - sbA) + off) = f2h2(v10, v11);
                    acc[i][j][0] = acc[i][j][1] = acc[i][j][2] = acc[i][j][3] = 0.f;
                }
            }
            __syncthreads();        // A rewrite complete before layer-2 reads
        }

        if (g + 3 < 16) issue_chunk(g + 3, smem, t);   // buf (g-1)&3, consumed

        const char* bbuf = smem + SMEM_B + (g & 3) * BCHUNK;
        #pragma unroll
        for (int kk = 0; kk < 2; ++kk) {
            int ktl = (g & 7) * 2 + kk;               // layer-local ktile 0..15
            uint32_t a[2][4];
            #pragma unroll
            for (int i = 0; i < 2; ++i) {
                int row = (wm * 2 + i) * 16 + (lane & 15);
                uint32_t addr = a_addr(sbA, row, ktl * 2 + (lane >> 4));
                asm volatile("ldmatrix.sync.aligned.m8n8.x4.shared.b16 {%0,%1,%2,%3}, [%4];"
                             : "=r"(a[i][0]), "=r"(a[i][1]), "=r"(a[i][2]), "=r"(a[i][3])
                             : "r"(addr));
            }
            uint4 bf[4];
            #pragma unroll
            for (int jp = 0; jp < 4; ++jp)
                bf[jp] = *(const uint4*)(bbuf + ((kk * 16 + wn * 4 + jp) * 32 + lane) * 16);
            #pragma unroll
            for (int i = 0; i < 2; ++i)
                #pragma unroll
                for (int jp = 0; jp < 4; ++jp) {
                    mma_f16(acc[i][jp * 2 + 0], a[i], bf[jp].x, bf[jp].y);
                    mma_f16(acc[i][jp * 2 + 1], a[i], bf[jp].z, bf[jp].w);
                }
        }
    }

    // ---- final: bias+relu, dot w3, reduce ----------------------------------
    {
        float rsum[4] = {0.f, 0.f, 0.f, 0.f};
        #pragma unroll
        for (int i = 0; i < 2; ++i)
            #pragma unroll
            for (int j = 0; j < 8; ++j)
                #pragma unroll
                for (int h = 0; h < 2; ++h)
                    #pragma unroll
                    for (int e = 0; e < 2; ++e) {
                        int c = wn * 64 + j * 8 + 2 * (lane & 3) + e;
                        float v = fmaxf(acc[i][j][h * 2 + e] + sB2[c], 0.f);
                        rsum[i * 2 + h] = fmaf(v, sW3[c], rsum[i * 2 + h]);
                    }
        #pragma unroll
        for (int k = 0; k < 4; ++k) {
            rsum[k] += __shfl_xor_sync(0xffffffffu, rsum[k], 1);
            rsum[k] += __shfl_xor_sync(0xffffffffu, rsum[k], 2);
        }
        float* red = (float*)(smem + SMEM_RED);
        if ((lane & 3) == 0) {
            #pragma unroll
            for (int i = 0; i < 2; ++i)
                #pragma unroll
                for (int h = 0; h < 2; ++h)
                    red[wn * 64 + wm * 32 + i * 16 + h * 8 + (lane >> 2)] = rsum[i * 2 + h];
        }
    }
    __syncthreads();
    if (t < TM) {
        int gi = m0 + t;
        float* red = (float*)(smem + SMEM_RED);
        if (gi < M)
            out[gi] = red[t] + red[64 + t] + red[128 + t] + red[192 + t] + __ldg(b3v);
    }
}

// ------------------------------------------------------------- launch
extern "C" void kernel_launch(void* const* d_in, const int* in_sizes, int n_in,
                              void* d_out, int out_size)
{
    const int*   pv = (const int*)d_in[0];
    const int*   qv = (const int*)d_in[1];
    const float* E  = (const float*)d_in[2];
    const float* w1 = (const float*)d_in[3];
    const float* b1 = (const float*)d_in[4];
    const float* w2 = (const float*)d_in[5];
    const float* b2 = (const float*)d_in[6];
    const float* w3 = (const float*)d_in[7];
    const float* b3 = (const float*)d_in[8];
    float* out = (float*)d_out;
    const int M = in_sizes[0];

    cudaFuncSetAttribute(fused_mlp_mma,
                         cudaFuncAttributeMaxDynamicSharedMemorySize, SMEM_TOTAL);

    pack_w_kernel<<<64, 256>>>(w1, w2);
    int grid = (M + TM - 1) / TM;
    fused_mlp_mma<<<grid, NTH, SMEM_TOTAL>>>(pv, qv, E, b1, b2, w3, b3, out, M);
}

// round 8
// speedup vs baseline: 5.2118x; 1.7074x over previous
#include <cuda_runtime.h>
#include <cuda_fp16.h>
#include <cstdint>

#define D        256
#define TM       64
#define NTH      256

// smem layout (bytes)
#define SMEM_A     0          // A fp16 row-major: 64 rows x 512B (swizzled) = 32768
#define SMEM_SB1   32768      // 256 floats
#define SMEM_SB2   33792
#define SMEM_SW3   34816
#define SMEM_RED   35840      // 512 floats
#define SMEM_TOTAL 37888

// frag-packed fp16 weights: [layer(2)][ktile(16)][slot(16)][lane(32)] x 16B
// slot s holds ntiles 2s, 2s+1; per lane: {b0(2s), b1(2s), b0(2s+1), b1(2s+1)}
__device__ uint4 g_bpack[2 * 16 * 16 * 32];

__device__ __forceinline__ uint32_t f2h2(float lo, float hi) {
    __half2 h = __floats2half2_rn(lo, hi);
    return *(uint32_t*)&h;
}

__device__ __forceinline__ void mma_f16(float* c, const uint32_t* a, uint32_t b0, uint32_t b1) {
    asm volatile("mma.sync.aligned.m16n8k16.row.col.f32.f16.f16.f32 "
                 "{%0,%1,%2,%3}, {%4,%5,%6,%7}, {%8,%9}, {%0,%1,%2,%3};"
                 : "+f"(c[0]), "+f"(c[1]), "+f"(c[2]), "+f"(c[3])
                 : "r"(a[0]), "r"(a[1]), "r"(a[2]), "r"(a[3]), "r"(b0), "r"(b1));
}

// ------------------------------------------------------------- weight prep
__global__ void pack_w_kernel(const float* __restrict__ w1, const float* __restrict__ w2) {
    int idx = blockIdx.x * 256 + threadIdx.x;      // 16384 uint4 slots
    int l    = idx >> 13;
    int kt   = (idx >> 9) & 15;
    int s    = (idx >> 5) & 15;
    int lane = idx & 31;
    const float* w = l ? w2 : w1;
    int g = lane >> 2, t = lane & 3;
    int k0 = kt * 16 + 2 * t;
    int na = 16 * s + g;
    int nb = na + 8;
    uint4 v;
    v.x = f2h2(w[(k0    ) * D + na], w[(k0 + 1) * D + na]);
    v.y = f2h2(w[(k0 + 8) * D + na], w[(k0 + 9) * D + na]);
    v.z = f2h2(w[(k0    ) * D + nb], w[(k0 + 1) * D + nb]);
    v.w = f2h2(w[(k0 + 8) * D + nb], w[(k0 + 9) * D + nb]);
    g_bpack[idx] = v;
}

// A smem address: row-major fp16, 512B rows, 16B-unit swizzle u^(row&7)
__device__ __forceinline__ uint32_t a_addr(uint32_t sbA, int row, int unit) {
    return sbA + row * 512 + (((unsigned)(unit ^ (row & 7))) << 4);
}

// ------------------------------------------------------------- main kernel
__global__ __launch_bounds__(NTH, 2)
void fused_mlp_mma(const int* __restrict__ pv, const int* __restrict__ qv,
                   const float* __restrict__ E,
                   const float* __restrict__ b1v, const float* __restrict__ b2v,
                   const float* __restrict__ w3v, const float* __restrict__ b3v,
                   float* __restrict__ out, int M)
{
    extern __shared__ char smem[];
    uint32_t sbA;
    asm("{ .reg .u64 u; cvta.to.shared.u64 u, %1; cvt.u32.u64 %0, u; }" : "=r"(sbA) : "l"(smem));
    const int t = threadIdx.x, lane = t & 31, wn = t >> 5;  // warp = full M x 32 cols
    const int m0 = blockIdx.x * TM;

    float* sB1 = (float*)(smem + SMEM_SB1);
    float* sB2 = (float*)(smem + SMEM_SB2);
    float* sW3 = (float*)(smem + SMEM_SW3);
    sB1[t] = b1v[t]; sB2[t] = b2v[t]; sW3[t] = w3v[t];   // NTH == D

    // ---- gather + sqdiff -> A rows (fp16), conflict-free STS.128 ------------
    {
        int r = t >> 2, part = t & 3;              // 4 threads per row, 64 cols each
        int gi = m0 + r;
        int pi = (gi < M) ? pv[gi] : 0;
        int qi = (gi < M) ? qv[gi] : 0;
        const float4* P = (const float4*)(E + (size_t)pi * D) + part * 16;
        const float4* Q = (const float4*)(E + (size_t)qi * D) + part * 16;
        #pragma unroll
        for (int jj = 0; jj < 8; ++jj) {
            float4 a0 = __ldg(P + 2 * jj),     b0 = __ldg(Q + 2 * jj);
            float4 a1 = __ldg(P + 2 * jj + 1), b1 = __ldg(Q + 2 * jj + 1);
            float d0 = a0.x - b0.x, d1 = a0.y - b0.y, d2 = a0.z - b0.z, d3 = a0.w - b0.w;
            float e0 = a1.x - b1.x, e1 = a1.y - b1.y, e2 = a1.z - b1.z, e3 = a1.w - b1.w;
            uint4 v;
            v.x = f2h2(d0 * d0, d1 * d1);
            v.y = f2h2(d2 * d2, d3 * d3);
            v.z = f2h2(e0 * e0, e1 * e1);
            v.w = f2h2(e2 * e2, e3 * e3);
            *(uint4*)(smem + (a_addr(sbA, r, part * 8 + jj) - sbA)) = v;
        }
    }
    __syncthreads();

    float acc[4][4][4];
    #pragma unroll
    for (int m = 0; m < 4; ++m)
        #pragma unroll
        for (int n = 0; n < 4; ++n)
            #pragma unroll
            for (int e = 0; e < 4; ++e) acc[m][n][e] = 0.f;

    // ---- two layers, barrier-free mainloop, B straight from L1/L2 ----------
    #pragma unroll 1
    for (int layer = 0; layer < 2; ++layer) {
        const uint4* bw = g_bpack + (size_t)layer * (16 * 16 * 32);
        // 2-deep B prefetch (per-warp private fragments)
        uint4 bpre[2][2];
        #pragma unroll
        for (int pf = 0; pf < 2; ++pf)
            #pragma unroll
            for (int j = 0; j < 2; ++j)
                bpre[pf][j] = __ldg(bw + ((pf * 16 + wn * 2 + j) * 32 + lane));

        #pragma unroll
        for (int ktl = 0; ktl < 16; ++ktl) {
            uint32_t a[4][4];
            #pragma unroll
            for (int m = 0; m < 4; ++m) {
                int row = m * 16 + (lane & 15);
                uint32_t addr = a_addr(sbA, row, ktl * 2 + (lane >> 4));
                asm volatile("ldmatrix.sync.aligned.m8n8.x4.shared.b16 {%0,%1,%2,%3}, [%4];"
                             : "=r"(a[m][0]), "=r"(a[m][1]), "=r"(a[m][2]), "=r"(a[m][3])
                             : "r"(addr));
            }
            uint4 b0 = bpre[ktl & 1][0], b1 = bpre[ktl & 1][1];
            if (ktl + 2 < 16) {
                #pragma unroll
                for (int j = 0; j < 2; ++j)
                    bpre[ktl & 1][j] = __ldg(bw + (((ktl + 2) * 16 + wn * 2 + j) * 32 + lane));
            }
            #pragma unroll
            for (int m = 0; m < 4; ++m) {
                mma_f16(acc[m][0], a[m], b0.x, b0.y);
                mma_f16(acc[m][1], a[m], b0.z, b0.w);
                mma_f16(acc[m][2], a[m], b1.x, b1.y);
                mma_f16(acc[m][3], a[m], b1.z, b1.w);
            }
        }

        if (layer == 0) {
            // layer-1 epilogue: acc -> bias+relu -> fp16 A (warp's 32 cols)
            __syncthreads();       // all warps done READING layer-1 A
            #pragma unroll
            for (int m = 0; m < 4; ++m) {
                int r0 = m * 16 + (lane >> 2);
                #pragma unroll
                for (int nt = 0; nt < 4; ++nt) {
                    int c0 = wn * 32 + nt * 8 + 2 * (lane & 3);
                    float v00 = fmaxf(acc[m][nt][0] + sB1[c0],     0.f);
                    float v01 = fmaxf(acc[m][nt][1] + sB1[c0 + 1], 0.f);
                    float v10 = fmaxf(acc[m][nt][2] + sB1[c0],     0.f);
                    float v11 = fmaxf(acc[m][nt][3] + sB1[c0 + 1], 0.f);
                    int u = wn * 4 + nt;
                    int off = (c0 & 7) * 2;
                    *(uint32_t*)(smem + (a_addr(sbA, r0,     u) - sbA) + off) = f2h2(v00, v01);
                    *(uint32_t*)(smem + (a_addr(sbA, r0 + 8, u) - sbA) + off) = f2h2(v10, v11);
                    acc[m][nt][0] = acc[m][nt][1] = acc[m][nt][2] = acc[m][nt][3] = 0.f;
                }
            }
            __syncthreads();       // A rewrite complete before layer-2 reads
        }
    }

    // ---- final: bias+relu, dot w3, reduce ----------------------------------
    {
        float rsum[8];
        #pragma unroll
        for (int k = 0; k < 8; ++k) rsum[k] = 0.f;
        #pragma unroll
        for (int m = 0; m < 4; ++m)
            #pragma unroll
            for (int nt = 0; nt < 4; ++nt)
                #pragma unroll
                for (int h = 0; h < 2; ++h)
                    #pragma unroll
                    for (int e = 0; e < 2; ++e) {
                        int c = wn * 32 + nt * 8 + 2 * (lane & 3) + e;
                        float v = fmaxf(acc[m][nt][h * 2 + e] + sB2[c], 0.f);
                        rsum[m * 2 + h] = fmaf(v, sW3[c], rsum[m * 2 + h]);
                    }
        #pragma unroll
        for (int k = 0; k < 8; ++k) {
            rsum[k] += __shfl_xor_sync(0xffffffffu, rsum[k], 1);
            rsum[k] += __shfl_xor_sync(0xffffffffu, rsum[k], 2);
        }
        float* red = (float*)(smem + SMEM_RED);
        if ((lane & 3) == 0) {
            #pragma unroll
            for (int m = 0; m < 4; ++m)
                #pragma unroll
                for (int h = 0; h < 2; ++h)
                    red[wn * 64 + m * 16 + h * 8 + (lane >> 2)] = rsum[m * 2 + h];
        }
    }
    __syncthreads();
    if (t < TM) {
        int gi = m0 + t;
        float* red = (float*)(smem + SMEM_RED);
        if (gi < M) {
            float s = __ldg(b3v);
            #pragma unroll
            for (int w = 0; w < 8; ++w) s += red[w * 64 + t];
            out[gi] = s;
        }
    }
}

// ------------------------------------------------------------- launch
extern "C" void kernel_launch(void* const* d_in, const int* in_sizes, int n_in,
                              void* d_out, int out_size)
{
    const int*   pv = (const int*)d_in[0];
    const int*   qv = (const int*)d_in[1];
    const float* E  = (const float*)d_in[2];
    const float* w1 = (const float*)d_in[3];
    const float* b1 = (const float*)d_in[4];
    const float* w2 = (const float*)d_in[5];
    const float* b2 = (const float*)d_in[6];
    const float* w3 = (const float*)d_in[7];
    const float* b3 = (const float*)d_in[8];
    float* out = (float*)d_out;
    const int M = in_sizes[0];

    cudaFuncSetAttribute(fused_mlp_mma,
                         cudaFuncAttributeMaxDynamicSharedMemorySize, SMEM_TOTAL);

    pack_w_kernel<<<64, 256>>>(w1, w2);
    int grid = (M + TM - 1) / TM;
    fused_mlp_mma<<<grid, NTH, SMEM_TOTAL>>>(pv, qv, E, b1, b2, w3, b3, out, M);
}